// round 10
// baseline (speedup 1.0000x reference)
#include <cuda_runtime.h>

// Chamfer distance via fixed rank-window NN search (exact).
// array1, array2 [B=4, N=4096, D=3] fp32.
// out = (100/32768) * sum over all 32768 per-point NN sq-dists (both dirs).
//
// Prep: bucket-sort the 8 (batch,array) combos by x (512 buckets, [-6,6]).
// Search: queries processed in sorted order. A warp owns 16 consecutive
// queries x 2 candidate parities. It scans a FIXED window of +-PAD ranks
// around the group in ONE tight uniform loop (1 broadcast LDS.128 + 3 FFMA +
// 1 FMNMX per candidate -- R6 efficiency, no mid-loop control). Rank windows
// auto-adapt to density: tails are sparse so +-312 ranks spans a huge
// x-extent. After the scan, ONE coverage check: r = sqrt(max(sq-2M,0));
// window covers the query iff all unscanned candidates lie outside
// [qx-r, qx+r] in x, certified via the window-edge x values padded by one
// bucket width BW (within-bucket disorder bound: for i < gl,
// x_i <= x[gl-1]+BW; for i >= gr, x_i >= x[gr]-BW). Uncovered queries
// (~20/32768 expected) trigger a rare warp-uniform 128-chunk extension loop;
// M only grows, window only grows -> terminates; at termination the true NN
// is provably inside the scanned set -> min is exact and independent of
// within-bucket order -> deterministic.
//
// R9 failed on per-chunk control overhead (alu 16.8% > fma 7.7%); R10 hoists
// ALL control out of the hot loop. 21M pairs (15.6% of brute force).

#define NBK 512
#define XLO (-6.0f)
#define XINVW (NBK / 12.0f)
#define BW (12.0f / NBK)
#define NPTS 4096
#define PAD 312
#define WINBLK 768            // block window: 128 queries + 2*PAD, rounded
#define EXT 128
#define SBLK 256              // 8 combos x 32 blocks
#define NEG3 (-3.0e38f)

__device__ float4 g_sorted[8][NPTS];
__device__ float  g_partial[SBLK];
__device__ int    g_count;    // zero-init; self-resets each run

__device__ __forceinline__ int bucket_of(float x) {
    int bk = (int)((x - XLO) * XINVW);
    bk = bk < 0 ? 0 : bk;
    return bk > NBK - 1 ? NBK - 1 : bk;
}

// ---------------- kernel 1: bucket-sort the 8 arrays by x ----------------
__global__ __launch_bounds__(512) void chamfer_prep(
    const float* __restrict__ a1, const float* __restrict__ a2)
{
    __shared__ int sh[NBK];
    __shared__ int soff[NBK];

    const int c = blockIdx.x;            // combo 0..7 = b*2 + arr
    const int b = c >> 1;
    const float* src = ((c & 1) ? a2 : a1) + (size_t)b * NPTS * 3;
    const int t = threadIdx.x;           // 512 == NBK

    sh[t] = 0;
    __syncthreads();

    float px[8], py[8], pz[8];
    int   bk[8];
#pragma unroll
    for (int k = 0; k < 8; k++) {
        const int i = t + k * 512;
        px[k] = src[i * 3 + 0];
        py[k] = src[i * 3 + 1];
        pz[k] = src[i * 3 + 2];
        bk[k] = bucket_of(px[k]);
        atomicAdd(&sh[bk[k]], 1);
    }
    __syncthreads();

    for (int off = 1; off < NBK; off <<= 1) {     // inclusive scan
        const int v = (t >= off) ? sh[t - off] : 0;
        __syncthreads();
        sh[t] += v;
        __syncthreads();
    }

    soff[t] = (t == 0) ? 0 : sh[t - 1];
    __syncthreads();

#pragma unroll
    for (int k = 0; k < 8; k++) {
        const int r = atomicAdd(&soff[bk[k]], 1);
        g_sorted[c][r] = make_float4(px[k], py[k], pz[k],
            -0.5f * (px[k] * px[k] + py[k] * py[k] + pz[k] * pz[k]));
    }
}

// ---------------- kernel 2: fixed-window search ----------------
__global__ __launch_bounds__(256) void chamfer_search(float* __restrict__ out)
{
    __shared__ __align__(16) float4 swin[WINBLK];   // 12 KB block window
    __shared__ float s_red[8];
    __shared__ int   s_last;

    const int t   = threadIdx.x;
    const int wid = t >> 5, ln = t & 31;
    const int c   = blockIdx.x >> 5;          // query combo 0..7
    const int cc  = c ^ 1;                    // candidate combo
    const float4* __restrict__ cand = g_sorted[cc];

    const int blockQ0 = (blockIdx.x & 31) * 128;

    int winL = blockQ0 - PAD;
    winL = winL < 0 ? 0 : winL;
    if (winL > NPTS - WINBLK) winL = NPTS - WINBLK;

#pragma unroll
    for (int k = 0; k < 3; k++)               // 256 thr x 3 = 768 float4
        swin[t + k * 256] = cand[winL + t + k * 256];
    __syncthreads();

    // lane = query (ln&15) x candidate parity (ln>>4)
    const int par = ln >> 4;
    const int q   = blockQ0 + wid * 16 + (ln & 15);
    const float4 Q = g_sorted[c][q];
    const float qx = Q.x, qy = Q.y, qz = Q.z;
    const float sq = -2.0f * Q.w;             // |q|^2

    // group window (global ranks), guaranteed inside [winL, winL+WINBLK)
    const int qg0 = blockQ0 + wid * 16;
    int gl = qg0 - PAD;       gl = gl < 0 ? 0 : gl;
    int gr = qg0 + 16 + PAD;  gr = gr > NPTS ? NPTS : gr;

    // hot loop: zero control, broadcast LDS.128, 3 FFMA + 1 FMNMX per cand
    float M = NEG3;
    {
        const int lo = gl - winL + par;
        const int hi = gr - winL;
#pragma unroll 4
        for (int i = lo; i < hi; i += 2) {
            const float4 C = swin[i];
            M = fmaxf(M, fmaf(qx, C.x, fmaf(qy, C.y, fmaf(qz, C.z, C.w))));
        }
    }
    float Mq = fmaxf(M, __shfl_xor_sync(0xffffffffu, M, 16));

    // coverage check + rare extension (warp-uniform)
    while (true) {
        const float bd = fmaxf(fmaf(-2.0f, Mq, sq), 0.0f);
        const float r  = sqrtf(bd);
        bool covL = (gl == 0), covR = (gr == NPTS);
        if (!covL) covL = (qx - r) > (cand[gl - 1].x + BW);
        if (!covR) covR = (qx + r) < (cand[gr].x - BW);
        const unsigned needL = __ballot_sync(0xffffffffu, !covL);
        const unsigned needR = __ballot_sync(0xffffffffu, !covR);
        if (!(needL | needR)) break;
        if (needL) {
            int a = gl - EXT; a = a < 0 ? 0 : a;
            for (int i = a; i < gl; i++) {
                const float4 C = cand[i];
                M = fmaxf(M, fmaf(qx, C.x, fmaf(qy, C.y, fmaf(qz, C.z, C.w))));
            }
            gl = a;
        }
        if (needR) {
            int b2 = gr + EXT; b2 = b2 > NPTS ? NPTS : b2;
            for (int i = gr; i < b2; i++) {
                const float4 C = cand[i];
                M = fmaxf(M, fmaf(qx, C.x, fmaf(qy, C.y, fmaf(qz, C.z, C.w))));
            }
            gr = b2;
        }
        Mq = fmaxf(M, __shfl_xor_sync(0xffffffffu, M, 16));
    }

    // sum this warp's 16 query d2 values (each query lives on 2 lanes)
    const float d2 = fmaf(-2.0f, Mq, sq);
    float v = (ln < 16) ? d2 : 0.0f;
#pragma unroll
    for (int o = 16; o; o >>= 1) v += __shfl_xor_sync(0xffffffffu, v, o);
    if (ln == 0) s_red[wid] = v;
    __syncthreads();

    if (t == 0) {
        float rsum = 0.0f;
#pragma unroll
        for (int g = 0; g < 8; g++) rsum += s_red[g];
        g_partial[blockIdx.x] = rsum;
        __threadfence();
        const int old = atomicAdd(&g_count, 1);
        s_last = (old == SBLK - 1);
    }
    __syncthreads();

    // last block: warp 0 sums the 256 partials in fixed order (deterministic)
    if (s_last && wid == 0) {
        __threadfence();
        float s = 0.0f;
#pragma unroll
        for (int k = 0; k < SBLK / 32; k++) s += g_partial[ln + k * 32];
#pragma unroll
        for (int o = 16; o; o >>= 1) s += __shfl_down_sync(0xffffffffu, s, o);
        if (ln == 0) {
            out[0] = s * (100.0f / 32768.0f);
            g_count = 0;      // reset for next graph replay
        }
    }
}

extern "C" void kernel_launch(void* const* d_in, const int* in_sizes, int n_in,
                              void* d_out, int out_size)
{
    const float* a1 = (const float*)d_in[0];
    const float* a2 = (const float*)d_in[1];
    float* out = (float*)d_out;

    chamfer_prep<<<8, 512>>>(a1, a2);
    chamfer_search<<<SBLK, 256>>>(out);
}

// round 11
// speedup vs baseline: 2.6600x; 2.6600x over previous
#include <cuda_runtime.h>

// Chamfer distance, brute force at the FFMA rt=2 ceiling, persistent tiles.
// array1, array2 [B=4, N=4096, D=3] fp32.
// out = (100/32768) * sum over all 32768 per-point NN sq-dists (both dirs).
//
// d2 = |a|^2 + |b|^2 - 2 a.b; smem candidate tile holds (x,y,z,-0.5|y|^2);
// per pair: 3 FFMA + 1 FMNMX (alu pipe); min d2 = sq - 2*max t. This loop is
// proven (R6: 96% of the fma-pipe ceiling). R7-R10 pruning attempts all lost
// to control overhead -- abandoned.
//
// R6 wasted 24 of 152 SMs (grid 128). R11: PERSISTENT kernel, 152 CTAs x 512
// threads, 1024 tiles = (combo 0..7) x (query-block 0..31 of 128) x (inner
// quarter 0..3 of 1024 candidates), fetched via atomic counter. Dynamic
// assignment is nondeterministic but each tile's partial min goes to a slot
// fixed by tile id, and min/sum are recombined in fixed order by the last
// finisher -> bit-deterministic. Counters self-reset for graph replay.

#define BLK 512
#define NWARP 16
#define PT 4
#define QBLK 128
#define NPTS 4096
#define QUARTER 1024
#define SLICE 64              // QUARTER / NWARP
#define NTILES 1024           // 8 * 32 * 4
#define NCTA 152

__device__ float g_qmin[NTILES][QBLK];   // 512 KB partial mins
__device__ int   g_tile;     // zero-init; self-resets
__device__ int   g_done;     // zero-init; self-resets

__global__ __launch_bounds__(BLK) void chamfer_persist(
    const float* __restrict__ a1, const float* __restrict__ a2,
    float* __restrict__ out)
{
    __shared__ __align__(16) float4 scand[QUARTER];      // 16 KB
    __shared__ float s_part[NWARP][QBLK];                // 8 KB
    __shared__ float s_red[NWARP];
    __shared__ int   s_tile;
    __shared__ int   s_lastflag;

    const int t  = threadIdx.x;
    const int wi = t >> 5;
    const int l  = t & 31;

    // ---------------- phase 1: dynamic tile loop ----------------
    while (true) {
        if (t == 0) s_tile = atomicAdd(&g_tile, 1);
        __syncthreads();
        const int tile = s_tile;
        if (tile >= NTILES) break;

        const int c  = tile >> 7;            // combo 0..7 = b*2 + arr
        const int qb = (tile >> 2) & 31;     // query block
        const int qr = tile & 3;             // inner quarter
        const int b  = c >> 1;

        const float* xb = ((c & 1) ? a2 : a1) + (size_t)b * NPTS * 3;  // queries
        const float* yb = ((c & 1) ? a1 : a2) + (size_t)b * NPTS * 3;  // candidates

        // fill candidate quarter: threads 0..255, 4 points each (3 float4)
        if (t < 256) {
            const float4* ysrc = (const float4*)yb + (size_t)qr * (QUARTER * 3 / 4);
            const float4 A = ysrc[t * 3 + 0];
            const float4 B = ysrc[t * 3 + 1];
            const float4 C = ysrc[t * 3 + 2];
            scand[t * 4 + 0] = make_float4(A.x, A.y, A.z,
                -0.5f * (A.x * A.x + A.y * A.y + A.z * A.z));
            scand[t * 4 + 1] = make_float4(A.w, B.x, B.y,
                -0.5f * (A.w * A.w + B.x * B.x + B.y * B.y));
            scand[t * 4 + 2] = make_float4(B.z, B.w, C.x,
                -0.5f * (B.z * B.z + B.w * B.w + C.x * C.x));
            scand[t * 4 + 3] = make_float4(C.y, C.z, C.w,
                -0.5f * (C.y * C.y + C.z * C.z + C.w * C.w));
        }

        // load this lane's PT=4 queries (L2-hot after first tile)
        const int n0 = qb * QBLK + l;
        float ax[PT], ay[PT], az[PT], sq[PT], m[PT];
#pragma unroll
        for (int k = 0; k < PT; k++) {
            const int n = n0 + k * 32;
            ax[k] = xb[n * 3 + 0];
            ay[k] = xb[n * 3 + 1];
            az[k] = xb[n * 3 + 2];
            sq[k] = ax[k] * ax[k] + ay[k] * ay[k] + az[k] * az[k];
            m[k]  = -3.0e38f;
        }
        __syncthreads();

        // hot loop: warp wi scans its 64-candidate slice (broadcast LDS.128)
        const float4* syp = scand + (size_t)wi * SLICE;
#pragma unroll 4
        for (int i = 0; i < SLICE; i++) {
            const float4 p = syp[i];
#pragma unroll
            for (int k = 0; k < PT; k++) {
                const float tt = fmaf(ax[k], p.x,
                                 fmaf(ay[k], p.y,
                                 fmaf(az[k], p.z, p.w)));
                m[k] = fmaxf(m[k], tt);
            }
        }

        // per-warp partials -> cross-warp min -> fixed slot g_qmin[tile][*]
#pragma unroll
        for (int k = 0; k < PT; k++)
            s_part[wi][l + k * 32] = sq[k] - 2.0f * m[k];
        __syncthreads();

        if (t < QBLK) {
            float v = s_part[0][t];
#pragma unroll
            for (int g = 1; g < NWARP; g++) v = fminf(v, s_part[g][t]);
            g_qmin[tile][t] = v;
        }
        // loop-top __syncthreads protects scand/s_part reuse
    }

    // ---------------- phase 2: last finisher reduces ----------------
    __syncthreads();
    if (t == 0) {
        __threadfence();
        const int old = atomicAdd(&g_done, 1);
        s_lastflag = (old == NCTA - 1);
    }
    __syncthreads();
    if (!s_lastflag) return;
    __threadfence();

    // 32768 queries: min over 4 quarters, then sum (fixed order per thread)
    float acc = 0.0f;
#pragma unroll 1
    for (int k = 0; k < 64; k++) {
        const int gq = t + k * BLK;          // global query id
        const int c  = gq >> 12;
        const int qb = (gq >> 7) & 31;
        const int ql = gq & 127;
        const int bt = c * 128 + qb * 4;
        const float v = fminf(fminf(g_qmin[bt + 0][ql], g_qmin[bt + 1][ql]),
                              fminf(g_qmin[bt + 2][ql], g_qmin[bt + 3][ql]));
        acc += v;
    }
#pragma unroll
    for (int o = 16; o; o >>= 1) acc += __shfl_down_sync(0xffffffffu, acc, o);
    if (l == 0) s_red[wi] = acc;
    __syncthreads();

    if (t == 0) {
        float s = 0.0f;
#pragma unroll
        for (int g = 0; g < NWARP; g++) s += s_red[g];
        out[0] = s * (100.0f / 32768.0f);
        g_tile = 0;          // reset for next graph replay
        g_done = 0;
    }
}

extern "C" void kernel_launch(void* const* d_in, const int* in_sizes, int n_in,
                              void* d_out, int out_size)
{
    const float* a1 = (const float*)d_in[0];
    const float* a2 = (const float*)d_in[1];
    float* out = (float*)d_out;

    chamfer_persist<<<NCTA, BLK>>>(a1, a2, out);
}

// round 13
// speedup vs baseline: 2.8308x; 1.0642x over previous
#include <cuda_runtime.h>

// Chamfer distance, brute force with DOT-SHARING between the two directions.
// array1, array2 [B=4, N=4096, D=3] fp32.
// out = (100/32768) * sum over all 32768 per-point NN sq-dists (both dirs).
//
// Both directions of one batch use the SAME 4096x4096 dot matrix. Per pair
// compute t = q.c + w once (w = -0.5|c|^2, 3 FFMA):
//   row (query's NN among candidates):  d2_row = sq - 2*max_c t
//   col (candidate's NN among queries): d2_col = -2 * max_q (t + qoff),
//       qoff = -0.5|q|^2 (1 FADD)      [because |c|^2 + 2w = 0]
// fma-pipe ops per candidate-warp: 12 FFMA + 4 FADD = 16 (32 cyc at rt=2)
// vs 24 FFMA (48 cyc) when directions are computed independently (R6, which
// provably saturated that ceiling at 0.51 FFMA/cyc/SMSP).
//
// Column combine (R12 fix: redux.f32 doesn't exist on sm_103):
//   per-lane float -> order-preserving uint key (u ^ ((s>>31)|0x80000000)),
//   warp max via __reduce_max_sync (u32 redux, Ampere+), lane0 atomicMax to
//   g_colkey. atomicMax on uint is exact & order-independent -> deterministic.
//   Zero key = sentinel below every real key and every candidate is updated
//   by all 32 blocks of its batch -> zero-init needs no init kernel; the
//   finisher resets keys to 0 -> graph-replay safe. Single kernel.
//
// Grid: 128 blocks (4 batches x 32 row-blocks of 128 queries), 512 threads.
// Lane owns PT=4 queries; candidates stream through a 32 KB smem tile
// (2 passes x 2048); warp wi owns a 128-candidate slice per pass.
// Rows: cross-warp min via smem, block sum -> g_partial. Last finisher
// (atomic counter) sums row partials + decodes/sums col keys -> out.

#define BLK 512
#define NWARP 16
#define PT 4
#define QBLK 128
#define NPTS 4096
#define PASS_PTS 2048
#define NPASS 2
#define SLICE 128            // PASS_PTS / NWARP
#define NBLOCKS 128
#define NEG3 (-3.0e38f)

__device__ unsigned int g_colkey[4][NPTS];   // zero-init; self-resets
__device__ float        g_partial[NBLOCKS];
__device__ int          g_count;             // zero-init; self-resets

__device__ __forceinline__ unsigned int fkey(float f) {
    const unsigned int u = __float_as_uint(f);
    return u ^ ((unsigned int)(((int)u) >> 31) | 0x80000000u);
}
__device__ __forceinline__ float fkey_dec(unsigned int k) {
    const unsigned int u = (k & 0x80000000u) ? (k ^ 0x80000000u) : ~k;
    return __uint_as_float(u);
}

__global__ __launch_bounds__(BLK) void chamfer_main(
    const float* __restrict__ a1, const float* __restrict__ a2,
    float* __restrict__ out)
{
    __shared__ __align__(16) float4 scand[PASS_PTS];     // 32 KB
    __shared__ float s_part[NWARP][QBLK];                // 8 KB
    __shared__ float s_red[4];
    __shared__ int   s_last;

    const int t  = threadIdx.x;
    const int wi = t >> 5;
    const int l  = t & 31;
    const int b  = blockIdx.x >> 5;          // batch 0..3
    const int rb = blockIdx.x & 31;          // row-block 0..31

    const float* xb = a1 + (size_t)b * NPTS * 3;   // queries (rows)
    const float* yb = a2 + (size_t)b * NPTS * 3;   // candidates (cols)

    // PT=4 queries per lane (same 128 queries in every warp)
    const int n0 = rb * QBLK + l;
    float ax[PT], ay[PT], az[PT], sq[PT], qoff[PT], m[PT];
#pragma unroll
    for (int k = 0; k < PT; k++) {
        const int n = n0 + k * 32;
        ax[k]   = xb[n * 3 + 0];
        ay[k]   = xb[n * 3 + 1];
        az[k]   = xb[n * 3 + 2];
        sq[k]   = ax[k] * ax[k] + ay[k] * ay[k] + az[k] * az[k];
        qoff[k] = -0.5f * sq[k];
        m[k]    = NEG3;
    }

#pragma unroll 1
    for (int pass = 0; pass < NPASS; pass++) {
        __syncthreads();   // previous tile fully consumed
        {   // 512 threads fill 4 candidates each (3 float4 LDG, 4 STS.128)
            const float4* ysrc = (const float4*)yb + (size_t)pass * (PASS_PTS * 3 / 4);
            const float4 A = ysrc[t * 3 + 0];
            const float4 B = ysrc[t * 3 + 1];
            const float4 C = ysrc[t * 3 + 2];
            scand[t * 4 + 0] = make_float4(A.x, A.y, A.z,
                -0.5f * (A.x * A.x + A.y * A.y + A.z * A.z));
            scand[t * 4 + 1] = make_float4(A.w, B.x, B.y,
                -0.5f * (A.w * A.w + B.x * B.x + B.y * B.y));
            scand[t * 4 + 2] = make_float4(B.z, B.w, C.x,
                -0.5f * (B.z * B.z + B.w * B.w + C.x * C.x));
            scand[t * 4 + 3] = make_float4(C.y, C.z, C.w,
                -0.5f * (C.y * C.y + C.z * C.z + C.w * C.w));
        }
        __syncthreads();

        // warp wi scans its 128-candidate slice (broadcast LDS.128)
        const float4* syp = scand + (size_t)wi * SLICE;
        const int cbase = pass * PASS_PTS + wi * SLICE;
#pragma unroll 4
        for (int i = 0; i < SLICE; i++) {
            const float4 p = syp[i];
            float cm = NEG3;
#pragma unroll
            for (int k = 0; k < PT; k++) {
                const float tt = fmaf(ax[k], p.x,
                                 fmaf(ay[k], p.y,
                                 fmaf(az[k], p.z, p.w)));
                m[k] = fmaxf(m[k], tt);            // row direction
                cm   = fmaxf(cm, tt + qoff[k]);    // col direction
            }
            const unsigned int ck = __reduce_max_sync(0xffffffffu, fkey(cm));
            if (l == 0) atomicMax(&g_colkey[b][cbase + i], ck);
        }
    }

    // row direction: cross-warp min, then block sum
#pragma unroll
    for (int k = 0; k < PT; k++)
        s_part[wi][l + k * 32] = sq[k] - 2.0f * m[k];
    __syncthreads();

    if (t < QBLK) {
        float v = s_part[0][t];
#pragma unroll
        for (int g = 1; g < NWARP; g++) v = fminf(v, s_part[g][t]);
#pragma unroll
        for (int o = 16; o; o >>= 1) v += __shfl_xor_sync(0xffffffffu, v, o);
        if (l == 0) s_red[wi] = v;
    }
    __syncthreads();

    if (t == 0) {
        g_partial[blockIdx.x] = s_red[0] + s_red[1] + s_red[2] + s_red[3];
        __threadfence();
        const int old = atomicAdd(&g_count, 1);
        s_last = (old == NBLOCKS - 1);
    }
    __syncthreads();
    if (!s_last) return;
    __threadfence();

    // ---- last finisher: rows + cols, fixed order -> deterministic ----
    float acc = 0.0f;
    // col sums: 4*4096 keys, 32 per thread; d2_col = -2 * decoded max
    const unsigned int* ck = &g_colkey[0][0];
#pragma unroll
    for (int k = 0; k < 32; k++) {
        acc += -2.0f * fkey_dec(ck[t + k * BLK]);
    }
    // row sums: 128 block partials on the first 128 threads
    if (t < NBLOCKS) acc += g_partial[t];

#pragma unroll
    for (int o = 16; o; o >>= 1) acc += __shfl_xor_sync(0xffffffffu, acc, o);
    if (l == 0) s_part[0][wi] = acc;
    __syncthreads();

    if (t == 0) {
        float s = 0.0f;
#pragma unroll
        for (int g = 0; g < NWARP; g++) s += s_part[0][g];
        out[0] = s * (100.0f / 32768.0f);
        g_count = 0;                       // reset for next graph replay
    }
    // reset col keys for next replay (identity = 0)
    {
        unsigned int* ckw = &g_colkey[0][0];
#pragma unroll
        for (int k = 0; k < 32; k++) ckw[t + k * BLK] = 0u;
    }
}

extern "C" void kernel_launch(void* const* d_in, const int* in_sizes, int n_in,
                              void* d_out, int out_size)
{
    const float* a1 = (const float*)d_in[0];
    const float* a2 = (const float*)d_in[1];
    float* out = (float*)d_out;

    chamfer_main<<<NBLOCKS, BLK>>>(a1, a2, out);
}

// round 14
// speedup vs baseline: 4.0692x; 1.4375x over previous
#include <cuda_runtime.h>
#include <cstdint>

// Chamfer distance, brute force, packed f32x2 FMA at the fma-pipe ceiling.
// array1, array2 [B=4, N=4096, D=3] fp32.
// out = (100/32768) * sum of per-point NN sq-dists (both dirs).
//
// d2 = |a|^2 + |b|^2 - 2 a.b. Candidates live in smem DUPLICATED per point:
// (x,x, y,y, z,z, w,w), w = -0.5|y|^2, so fma.rn.f32x2 (FFMA2) processes TWO
// query-points per instruction with zero packing movs in the loop.
// Per candidate per lane (PT=8 queries = 4 packed pairs):
//   2 LDS.128 + 12 FFMA2 + 8 FMNMX  -> fma-pipe 36 cyc (FFMA2 rt=3 banking)
// vs scalar R6: 24 FFMA -> 48 pipe-cyc. 0.75x pipe time; R6 measured 90%
// pipe-busy so the saving should show on the wall clock.
// R3-R5 packed attempts failed on asm-unpack MOVs + weak pipelining; here the
// FFMA2 result is read through a union (register-pair view, no MOVs) and the
// loop is unrolled 4 with 8 independent FMNMX accumulators.
//
// Grid 16x8 = 128 CTAs x 512 thr (4 warps/SMSP, proven regime). Each lane
// owns PT=8 queries; candidates stream through a 64 KB DYNAMIC smem tile
// (2 passes x 2048 cands x 32 B). Warp wi scans its 128-candidate slice.
// Cross-warp combine buffer overlays the dead tile. Final sum fused via
// atomic-counter last-block reduction (fixed read order -> deterministic;
// counter self-resets -> graph-replay safe).

#define BLK 512
#define NWARP 16
#define PT 8
#define QBLK 256
#define NCHUNK 16
#define NPTS 4096
#define PASS_PTS 2048
#define NPASS 2
#define SLICE 128            // PASS_PTS / NWARP
#define NBLOCKS 128
#define SMEM_BYTES (PASS_PTS * 32)   // 64 KB
#define NEG3 (-3.0e38f)

__device__ float g_partial[NBLOCKS];
__device__ int   g_count;    // zero-init; self-resets each run

__device__ __forceinline__ unsigned long long pack2(float lo, float hi) {
    unsigned long long r;
    asm("mov.b64 %0, {%1, %2};" : "=l"(r) : "f"(lo), "f"(hi));
    return r;
}
union U64F2 {
    unsigned long long u;
    float2 f;
};
__device__ __forceinline__ unsigned long long fma2(
    unsigned long long a, unsigned long long b, unsigned long long c) {
    unsigned long long d;
    asm("fma.rn.f32x2 %0, %1, %2, %3;" : "=l"(d) : "l"(a), "l"(b), "l"(c));
    return d;
}

__global__ __launch_bounds__(BLK) void chamfer_main(
    const float* __restrict__ a1, const float* __restrict__ a2,
    float* __restrict__ out)
{
    extern __shared__ char smem[];               // 64 KB dynamic
    __shared__ float s_red[NWARP];
    __shared__ int   s_last;

    const int t   = threadIdx.x;
    const int wi  = t >> 5;
    const int l   = t & 31;
    const int z   = blockIdx.y;                  // 0..7 = b*2 + dir
    const int b   = z >> 1;
    const int dir = z & 1;

    const float* xb = (dir ? a2 : a1) + (size_t)b * NPTS * 3;
    const float* yb = (dir ? a1 : a2) + (size_t)b * NPTS * 3;

    // PT=8 queries per lane, packed into 4 (ax,ay,az) pairs
    const int n0 = blockIdx.x * QBLK + l;
    unsigned long long ax2[4], ay2[4], az2[4];
    float sq[PT], m[PT];
#pragma unroll
    for (int j = 0; j < 4; j++) {
        const int na = n0 + (2 * j) * 32;
        const int nb = na + 32;
        const float xa = xb[na * 3 + 0], ya = xb[na * 3 + 1], za = xb[na * 3 + 2];
        const float xc = xb[nb * 3 + 0], yc = xb[nb * 3 + 1], zc = xb[nb * 3 + 2];
        ax2[j] = pack2(xa, xc);
        ay2[j] = pack2(ya, yc);
        az2[j] = pack2(za, zc);
        sq[2 * j + 0] = xa * xa + ya * ya + za * za;
        sq[2 * j + 1] = xc * xc + yc * yc + zc * zc;
        m[2 * j + 0] = NEG3;
        m[2 * j + 1] = NEG3;
    }

#pragma unroll 1
    for (int pass = 0; pass < NPASS; pass++) {
        __syncthreads();   // previous tile fully consumed
        {   // 512 threads fill 4 candidates each: 3 float4 LDG -> 8 STS.128
            const float4* ysrc = (const float4*)yb + (size_t)pass * (PASS_PTS * 3 / 4);
            const float4 A = ysrc[t * 3 + 0];
            const float4 B = ysrc[t * 3 + 1];
            const float4 C = ysrc[t * 3 + 2];
            float4* sp = (float4*)smem + (size_t)t * 8;
            float px, py, pz, pw;
            px = A.x; py = A.y; pz = A.z; pw = -0.5f * (px*px + py*py + pz*pz);
            sp[0] = make_float4(px, px, py, py);
            sp[1] = make_float4(pz, pz, pw, pw);
            px = A.w; py = B.x; pz = B.y; pw = -0.5f * (px*px + py*py + pz*pz);
            sp[2] = make_float4(px, px, py, py);
            sp[3] = make_float4(pz, pz, pw, pw);
            px = B.z; py = B.w; pz = C.x; pw = -0.5f * (px*px + py*py + pz*pz);
            sp[4] = make_float4(px, px, py, py);
            sp[5] = make_float4(pz, pz, pw, pw);
            px = C.y; py = C.z; pz = C.w; pw = -0.5f * (px*px + py*py + pz*pz);
            sp[6] = make_float4(px, px, py, py);
            sp[7] = make_float4(pz, pz, pw, pw);
        }
        __syncthreads();

        // warp wi scans its 128-candidate slice; 2 broadcast LDS.128 per cand
        const ulonglong2* syp = (const ulonglong2*)smem + (size_t)wi * SLICE * 2;
#pragma unroll 4
        for (int i = 0; i < SLICE; i++) {
            const ulonglong2 v0 = syp[2 * i + 0];   // (x,x)|(y,y)
            const ulonglong2 v1 = syp[2 * i + 1];   // (z,z)|(w,w)
#pragma unroll
            for (int j = 0; j < 4; j++) {
                U64F2 tt;
                tt.u = fma2(az2[j], v1.x, v1.y);
                tt.u = fma2(ay2[j], v0.y, tt.u);
                tt.u = fma2(ax2[j], v0.x, tt.u);
                m[2 * j + 0] = fmaxf(m[2 * j + 0], tt.f.x);
                m[2 * j + 1] = fmaxf(m[2 * j + 1], tt.f.y);
            }
        }
    }
    __syncthreads();   // tile dead; overlay combine array (16 x 256 = 16 KB)

    float (*s_part)[QBLK] = (float (*)[QBLK])smem;
#pragma unroll
    for (int k = 0; k < PT; k++)
        s_part[wi][l + k * 32] = sq[k] - 2.0f * m[k];
    __syncthreads();

    // first 256 threads: min across the 16 warp slices, then block-sum
    float v = 0.0f;
    if (t < QBLK) {
        v = s_part[0][t];
#pragma unroll
        for (int g = 1; g < NWARP; g++) v = fminf(v, s_part[g][t]);
    }
#pragma unroll
    for (int o = 16; o; o >>= 1) v += __shfl_xor_sync(0xffffffffu, v, o);
    if (l == 0) s_red[wi] = v;   // warps 8..15 contribute 0
    __syncthreads();

    if (t == 0) {
        float r = 0.0f;
#pragma unroll
        for (int g = 0; g < 8; g++) r += s_red[g];
        g_partial[blockIdx.y * NCHUNK + blockIdx.x] = r;
        __threadfence();
        const int old = atomicAdd(&g_count, 1);
        s_last = (old == NBLOCKS - 1);
    }
    __syncthreads();

    // last block: warp 0 sums the 128 partials in fixed order (deterministic)
    if (s_last && wi == 0) {
        __threadfence();
        float s = 0.0f;
#pragma unroll
        for (int q = 0; q < NBLOCKS / 32; q++) s += g_partial[l + q * 32];
#pragma unroll
        for (int o = 16; o; o >>= 1) s += __shfl_down_sync(0xffffffffu, s, o);
        if (l == 0) {
            out[0] = s * (100.0f / 32768.0f);
            g_count = 0;    // reset for next graph replay
        }
    }
}

extern "C" void kernel_launch(void* const* d_in, const int* in_sizes, int n_in,
                              void* d_out, int out_size)
{
    const float* a1 = (const float*)d_in[0];
    const float* a2 = (const float*)d_in[1];
    float* out = (float*)d_out;

    cudaFuncSetAttribute(chamfer_main,
                         cudaFuncAttributeMaxDynamicSharedMemorySize,
                         SMEM_BYTES);

    dim3 grid(NCHUNK, 8);               // 16 x 8 = 128 blocks, one wave
    chamfer_main<<<grid, BLK, SMEM_BYTES>>>(a1, a2, out);
}

// round 15
// speedup vs baseline: 4.3140x; 1.0601x over previous
#include <cuda_runtime.h>

// Chamfer distance: array1, array2 [B=4, N=4096, D=3] fp32.
// out = (100/32768) * sum of per-point NN sq-dists (both dirs).
//
// R15 = R6 (best kernel: main loop at ~90% of the FFMA rt=2 ceiling) with the
// separate reduce kernel FUSED via the atomic-counter last-block pattern
// (validated in R11/R13/R14): saves the ~2.7us second launch. The main loop
// is byte-for-byte R6's:
//   d2 = |a|^2 + |b|^2 - 2 a.b; smem tile (x,y,z,-0.5|y|^2); per pair
//   t = fma(ax,px, fma(ay,py, fma(az,pz,pw))); min d2 = sq - 2*max t.
//   3 FFMA (fma pipe, binding) + 1 FMNMX (alu pipe) per pair; 1 broadcast
//   LDS.128 per candidate amortized over PT=8 queries; 8 independent max
//   chains. Evidence: packed f32x2 (R3,R4,R5,R14), pruning (R7-R10),
//   persistence (R11), dot-sharing (R13) all lost to this loop.
//
// BLK=512 (4 warps/SMSP), grid 16x8 = 128 blocks = one wave. Warp owns 1/16
// of the inner tile; inner dim streamed in 2 passes of 2048 pts (32 KB smem).
// Cross-warp combine (16x256 = 16 KB) overlays the dead tile. Last block
// (atomic counter, fixed-order read -> deterministic; counter self-resets ->
// graph-replay safe) sums the 128 partials into d_out.

#define BLK 512
#define NWARP 16
#define PT 8
#define OUTER_PER_BLOCK 256
#define NCHUNK 16
#define NPTS 4096
#define PASS_PTS 2048
#define NPASS 2
#define SLICE 128            // PASS_PTS / NWARP
#define NBLOCKS 128

__device__ float g_partial[NBLOCKS];
__device__ int   g_count;    // zero-init; self-resets each run

__global__ __launch_bounds__(BLK) void chamfer_main(
    const float* __restrict__ a1, const float* __restrict__ a2,
    float* __restrict__ out)
{
    // 32 KB buffer: inner tile during passes; reused as the 16x256 combine
    // array after the last pass.
    __shared__ __align__(16) float4 sbuf[PASS_PTS];
    __shared__ float s_red[NWARP];
    __shared__ int   s_last;

    const int t   = threadIdx.x;
    const int wi  = t >> 5;            // warp id 0..15 = inner slice
    const int l   = t & 31;
    const int z   = blockIdx.y;        // 0..7 = b*2 + dir
    const int b   = z >> 1;
    const int dir = z & 1;

    const float* xb = (dir ? a2 : a1) + (size_t)b * NPTS * 3;
    const float* yb = (dir ? a1 : a2) + (size_t)b * NPTS * 3;

    // PT=8 outer points per lane (shared across all 16 warps)
    const int n0 = blockIdx.x * OUTER_PER_BLOCK + l;
    float ax[PT], ay[PT], az[PT], sq[PT], m[PT];
#pragma unroll
    for (int k = 0; k < PT; k++) {
        const int n = n0 + k * 32;
        ax[k] = xb[n * 3 + 0];
        ay[k] = xb[n * 3 + 1];
        az[k] = xb[n * 3 + 2];
        sq[k] = ax[k] * ax[k] + ay[k] * ay[k] + az[k] * az[k];
        m[k]  = -3.0e38f;
    }

#pragma unroll 1
    for (int pass = 0; pass < NPASS; pass++) {
        __syncthreads();   // previous tile fully consumed
        {   // all 512 threads fill 4 points each (3 float4 LDG, 4 STS.128)
            const float4* ysrc = (const float4*)yb + (size_t)pass * (PASS_PTS * 3 / 4);
            const float4 A = ysrc[t * 3 + 0];
            const float4 B = ysrc[t * 3 + 1];
            const float4 C = ysrc[t * 3 + 2];
            sbuf[t * 4 + 0] = make_float4(A.x, A.y, A.z,
                -0.5f * (A.x * A.x + A.y * A.y + A.z * A.z));
            sbuf[t * 4 + 1] = make_float4(A.w, B.x, B.y,
                -0.5f * (A.w * A.w + B.x * B.x + B.y * B.y));
            sbuf[t * 4 + 2] = make_float4(B.z, B.w, C.x,
                -0.5f * (B.z * B.z + B.w * B.w + C.x * C.x));
            sbuf[t * 4 + 3] = make_float4(C.y, C.z, C.w,
                -0.5f * (C.y * C.y + C.z * C.z + C.w * C.w));
        }
        __syncthreads();

        // warp wi scans its 128-point slice; broadcast LDS.128
        const float4* syp = sbuf + (size_t)wi * SLICE;
#pragma unroll 4
        for (int i = 0; i < SLICE; i++) {
            const float4 p = syp[i];
#pragma unroll
            for (int k = 0; k < PT; k++) {
                const float tt = fmaf(ax[k], p.x,
                                 fmaf(ay[k], p.y,
                                 fmaf(az[k], p.z, p.w)));
                m[k] = fmaxf(m[k], tt);
            }
        }
    }
    __syncthreads();   // tile dead; sbuf becomes the combine array

    float (*s_part)[OUTER_PER_BLOCK] = (float (*)[OUTER_PER_BLOCK])sbuf;
#pragma unroll
    for (int k = 0; k < PT; k++)
        s_part[wi][l + k * 32] = sq[k] - 2.0f * m[k];
    __syncthreads();

    // first 256 threads: min across the 16 inner slices, then block-sum
    float v = 0.0f;
    if (t < OUTER_PER_BLOCK) {
        v = s_part[0][t];
#pragma unroll
        for (int g = 1; g < NWARP; g++) v = fminf(v, s_part[g][t]);
    }
#pragma unroll
    for (int o = 16; o; o >>= 1) v += __shfl_xor_sync(0xffffffffu, v, o);
    if (l == 0) s_red[wi] = v;     // warps 8..15 contribute 0
    __syncthreads();

    if (t == 0) {
        float r = 0.0f;
#pragma unroll
        for (int g = 0; g < 8; g++) r += s_red[g];
        g_partial[blockIdx.y * NCHUNK + blockIdx.x] = r;
        __threadfence();
        const int old = atomicAdd(&g_count, 1);
        s_last = (old == NBLOCKS - 1);
    }
    __syncthreads();

    // last block: warp 0 sums the 128 partials in fixed order (deterministic)
    if (s_last && wi == 0) {
        __threadfence();
        float s = 0.0f;
#pragma unroll
        for (int q = 0; q < NBLOCKS / 32; q++) s += g_partial[l + q * 32];
#pragma unroll
        for (int o = 16; o; o >>= 1) s += __shfl_down_sync(0xffffffffu, s, o);
        if (l == 0) {
            out[0] = s * (100.0f / 32768.0f);
            g_count = 0;    // reset for next graph replay
        }
    }
}

extern "C" void kernel_launch(void* const* d_in, const int* in_sizes, int n_in,
                              void* d_out, int out_size)
{
    const float* a1 = (const float*)d_in[0];
    const float* a2 = (const float*)d_in[1];
    float* out = (float*)d_out;

    dim3 grid(NCHUNK, 8);               // 16 x 8 = 128 blocks, one wave
    chamfer_main<<<grid, BLK>>>(a1, a2, out);
}

// round 16
// speedup vs baseline: 4.9965x; 1.1582x over previous
#include <cuda_runtime.h>

// Chamfer distance: array1, array2 [B=4, N=4096, D=3] fp32.
// out = (100/32768) * sum of per-point NN sq-dists (both dirs).
//
// R16 = R15 (FFMA-pipe-saturated scalar loop, fused reduction) spread over
// ALL 152 SMs instead of 128. Grid = 8 combos x 19 blocks = 152. Each block
// owns 224 query slots (PT=7/lane); 19*224 = 4256 >= 4096, the overhang is
// DUMMY slots (query index clamped to 4095, computed uniformly, masked to 0
// in the reduction -> exact + deterministic + zero warp divergence in the
// hot loop). +3.9% redundant work, -15.8% per-SM work: 43.0K vs 49.2K
// fma-pipe cycles/SMSP.
//
// Hot loop per candidate per lane: 1 broadcast LDS.128 + 21 FFMA + 7 FMNMX;
// FFMA rt=2 binding (issue ~69%). Inner dim streamed in 2 passes of 2048
// candidates (32 KB smem tile: x,y,z,-0.5|y|^2). Warp owns 1/16 of the tile.
// Cross-warp combine (16x224 floats) overlays the dead tile. Last block
// (atomic counter, fixed-order read -> deterministic; self-resetting ->
// graph-replay safe) sums the 152 partials into d_out.

#define BLK 512
#define NWARP 16
#define PT 7
#define QPB 224              // 32 * PT query slots per block
#define BPC 19               // blocks per combo
#define NBLOCKS 152          // 8 * BPC
#define NPTS 4096
#define PASS_PTS 2048
#define NPASS 2
#define SLICE 128            // PASS_PTS / NWARP
#define NEG3 (-3.0e38f)

__device__ float g_partial[NBLOCKS];
__device__ int   g_count;    // zero-init; self-resets each run

__global__ __launch_bounds__(BLK) void chamfer_main(
    const float* __restrict__ a1, const float* __restrict__ a2,
    float* __restrict__ out)
{
    // 32 KB buffer: candidate tile during passes; 16x224 combine array after.
    __shared__ __align__(16) float4 sbuf[PASS_PTS];
    __shared__ float s_red[NWARP];
    __shared__ int   s_last;

    const int t   = threadIdx.x;
    const int wi  = t >> 5;            // warp id 0..15 = candidate slice
    const int l   = t & 31;
    const int z   = blockIdx.x / BPC;  // combo 0..7 = b*2 + dir
    const int j   = blockIdx.x - z * BPC;
    const int b   = z >> 1;
    const int dir = z & 1;

    const float* xb = (dir ? a2 : a1) + (size_t)b * NPTS * 3;
    const float* yb = (dir ? a1 : a2) + (size_t)b * NPTS * 3;

    // PT=7 query slots per lane; overhang slots clamp to 4095 (dummy)
    const int n0 = j * QPB + l;
    float ax[PT], ay[PT], az[PT], sq[PT], m[PT];
#pragma unroll
    for (int k = 0; k < PT; k++) {
        int n = n0 + k * 32;
        n = n < NPTS ? n : NPTS - 1;
        ax[k] = xb[n * 3 + 0];
        ay[k] = xb[n * 3 + 1];
        az[k] = xb[n * 3 + 2];
        sq[k] = ax[k] * ax[k] + ay[k] * ay[k] + az[k] * az[k];
        m[k]  = NEG3;
    }

#pragma unroll 1
    for (int pass = 0; pass < NPASS; pass++) {
        __syncthreads();   // previous tile fully consumed
        {   // all 512 threads fill 4 candidates each (3 float4 LDG, 4 STS.128)
            const float4* ysrc = (const float4*)yb + (size_t)pass * (PASS_PTS * 3 / 4);
            const float4 A = ysrc[t * 3 + 0];
            const float4 B = ysrc[t * 3 + 1];
            const float4 C = ysrc[t * 3 + 2];
            sbuf[t * 4 + 0] = make_float4(A.x, A.y, A.z,
                -0.5f * (A.x * A.x + A.y * A.y + A.z * A.z));
            sbuf[t * 4 + 1] = make_float4(A.w, B.x, B.y,
                -0.5f * (A.w * A.w + B.x * B.x + B.y * B.y));
            sbuf[t * 4 + 2] = make_float4(B.z, B.w, C.x,
                -0.5f * (B.z * B.z + B.w * B.w + C.x * C.x));
            sbuf[t * 4 + 3] = make_float4(C.y, C.z, C.w,
                -0.5f * (C.y * C.y + C.z * C.z + C.w * C.w));
        }
        __syncthreads();

        // warp wi scans its 128-candidate slice; broadcast LDS.128
        const float4* syp = sbuf + (size_t)wi * SLICE;
#pragma unroll 4
        for (int i = 0; i < SLICE; i++) {
            const float4 p = syp[i];
#pragma unroll
            for (int k = 0; k < PT; k++) {
                const float tt = fmaf(ax[k], p.x,
                                 fmaf(ay[k], p.y,
                                 fmaf(az[k], p.z, p.w)));
                m[k] = fmaxf(m[k], tt);
            }
        }
    }
    __syncthreads();   // tile dead; sbuf becomes the combine array

    float (*s_part)[QPB] = (float (*)[QPB])sbuf;
#pragma unroll
    for (int k = 0; k < PT; k++)
        s_part[wi][l + k * 32] = sq[k] - 2.0f * m[k];
    __syncthreads();

    // threads 0..223: min across the 16 slices; dummy slots masked to 0
    float v = 0.0f;
    if (t < QPB && (j * QPB + t) < NPTS) {
        v = s_part[0][t];
#pragma unroll
        for (int g = 1; g < NWARP; g++) v = fminf(v, s_part[g][t]);
    }
#pragma unroll
    for (int o = 16; o; o >>= 1) v += __shfl_xor_sync(0xffffffffu, v, o);
    if (l == 0) s_red[wi] = v;     // warps 7..15 contribute 0
    __syncthreads();

    if (t == 0) {
        float r = 0.0f;
#pragma unroll
        for (int g = 0; g < NWARP; g++) r += s_red[g];
        g_partial[blockIdx.x] = r;
        __threadfence();
        const int old = atomicAdd(&g_count, 1);
        s_last = (old == NBLOCKS - 1);
    }
    __syncthreads();

    // last block: warp 0 sums the 152 partials in fixed order (deterministic)
    if (s_last && wi == 0) {
        __threadfence();
        float s = 0.0f;
#pragma unroll
        for (int q = 0; q < 5; q++) {
            const int idx = l + q * 32;
            if (idx < NBLOCKS) s += g_partial[idx];
        }
#pragma unroll
        for (int o = 16; o; o >>= 1) s += __shfl_down_sync(0xffffffffu, s, o);
        if (l == 0) {
            out[0] = s * (100.0f / 32768.0f);
            g_count = 0;    // reset for next graph replay
        }
    }
}

extern "C" void kernel_launch(void* const* d_in, const int* in_sizes, int n_in,
                              void* d_out, int out_size)
{
    const float* a1 = (const float*)d_in[0];
    const float* a2 = (const float*)d_in[1];
    float* out = (float*)d_out;

    chamfer_main<<<NBLOCKS, BLK>>>(a1, a2, out);
}